// round 16
// baseline (speedup 1.0000x reference)
#include <cuda_runtime.h>
#include <math.h>

#define NB 64
#define NT 512
#define NV 512
#define NH 256
#define NO 512
#define MR (NB * NT)   // 32768 rows

// Scratch (allocation-free rule: __device__ globals)
__device__ float g_xproj[(size_t)MR * NH];   // x@W_ih^T + b_ih + b_hh
__device__ float g_hidden[(size_t)MR * NH];  // min(relu(h),1)

typedef unsigned long long ull;

__device__ __forceinline__ ull fma2(ull a, ull b, ull c) {
    ull d;
    asm("fma.rn.f32x2 %0, %1, %2, %3;" : "=l"(d) : "l"(a), "l"(b), "l"(c));
    return d;
}
__device__ __forceinline__ ull pack2(float lo, float hi) {
    ull r;
    unsigned int l = __float_as_uint(lo), h = __float_as_uint(hi);
    asm("mov.b64 %0, {%1, %2};" : "=l"(r) : "r"(l), "r"(h));
    return r;
}
__device__ __forceinline__ float2 unpack2(ull v) {
    unsigned int l, h;
    asm("mov.b64 {%0, %1}, %2;" : "=r"(l), "=r"(h) : "l"(v));
    return make_float2(__uint_as_float(l), __uint_as_float(h));
}

// ---------------------------------------------------------------------------
// GEMM (R4 version — measured 172us): BM=BN=128, BK=16, 256 threads,
// 8x8 micro-tile via f32x2 packed FMA, static double-buffered smem,
// one __syncthreads per k-tile.
// EPI==0: + bias1[n] + bias2[n]      EPI==1: sigmoid(x + bias1[n]) via __expf
// ---------------------------------------------------------------------------
template<int EPI>
__global__ void __launch_bounds__(256, 2)
gemm_nt(const float* __restrict__ A, const float* __restrict__ Bw,
        const float* __restrict__ bias1, const float* __restrict__ bias2,
        float* __restrict__ C, int M, int N, int K)
{
    __shared__ __align__(16) float As[2][16][132];
    __shared__ __align__(16) float Bs[2][16][132];
    const int tid = threadIdx.x;
    const int m0 = blockIdx.y << 7;
    const int n0 = blockIdx.x << 7;
    const int ar = tid >> 2;          // 0..63
    const int ac = (tid & 3) << 2;    // 0,4,8,12
    const float* Ag = A  + (size_t)(m0 + ar) * K + ac;
    const float* Bg = Bw + (size_t)(n0 + ar) * K + ac;
    const int tm = tid >> 4;          // 0..15 (row group of 8)
    const int tn = tid & 15;          // 0..15 (col group: tn*4 and tn*4+64)

    ull acc[4][8];
#pragma unroll
    for (int i = 0; i < 4; i++)
#pragma unroll
        for (int j = 0; j < 8; j++) acc[i][j] = 0ull;

    float4 a0 = *(const float4*)(Ag);
    float4 a1 = *(const float4*)(Ag + (size_t)64 * K);
    float4 b0 = *(const float4*)(Bg);
    float4 b1 = *(const float4*)(Bg + (size_t)64 * K);
    int buf = 0;
    {
        As[0][ac + 0][ar]      = a0.x; As[0][ac + 1][ar]      = a0.y;
        As[0][ac + 2][ar]      = a0.z; As[0][ac + 3][ar]      = a0.w;
        As[0][ac + 0][ar + 64] = a1.x; As[0][ac + 1][ar + 64] = a1.y;
        As[0][ac + 2][ar + 64] = a1.z; As[0][ac + 3][ar + 64] = a1.w;
        Bs[0][ac + 0][ar]      = b0.x; Bs[0][ac + 1][ar]      = b0.y;
        Bs[0][ac + 2][ar]      = b0.z; Bs[0][ac + 3][ar]      = b0.w;
        Bs[0][ac + 0][ar + 64] = b1.x; Bs[0][ac + 1][ar + 64] = b1.y;
        Bs[0][ac + 2][ar + 64] = b1.z; Bs[0][ac + 3][ar + 64] = b1.w;
    }
    __syncthreads();

    for (int k0 = 0; k0 < K; k0 += 16) {
        const bool more = (k0 + 16) < K;
        if (more) {
            Ag += 16; Bg += 16;
            a0 = *(const float4*)(Ag);
            a1 = *(const float4*)(Ag + (size_t)64 * K);
            b0 = *(const float4*)(Bg);
            b1 = *(const float4*)(Bg + (size_t)64 * K);
        }
#pragma unroll
        for (int k = 0; k < 16; k++) {
            ulonglong2 aA = *(const ulonglong2*)&As[buf][k][tm * 8];
            ulonglong2 aB = *(const ulonglong2*)&As[buf][k][tm * 8 + 4];
            float4 bA = *(const float4*)&Bs[buf][k][tn * 4];
            float4 bB = *(const float4*)&Bs[buf][k][tn * 4 + 64];
            ull a2[4] = { aA.x, aA.y, aB.x, aB.y };
            ull bb[8] = { pack2(bA.x, bA.x), pack2(bA.y, bA.y),
                          pack2(bA.z, bA.z), pack2(bA.w, bA.w),
                          pack2(bB.x, bB.x), pack2(bB.y, bB.y),
                          pack2(bB.z, bB.z), pack2(bB.w, bB.w) };
#pragma unroll
            for (int j = 0; j < 8; j++)
#pragma unroll
                for (int i = 0; i < 4; i++)
                    acc[i][j] = fma2(a2[i], bb[j], acc[i][j]);
        }
        if (more) {
            int nb = buf ^ 1;
            As[nb][ac + 0][ar]      = a0.x; As[nb][ac + 1][ar]      = a0.y;
            As[nb][ac + 2][ar]      = a0.z; As[nb][ac + 3][ar]      = a0.w;
            As[nb][ac + 0][ar + 64] = a1.x; As[nb][ac + 1][ar + 64] = a1.y;
            As[nb][ac + 2][ar + 64] = a1.z; As[nb][ac + 3][ar + 64] = a1.w;
            Bs[nb][ac + 0][ar]      = b0.x; Bs[nb][ac + 1][ar]      = b0.y;
            Bs[nb][ac + 2][ar]      = b0.z; Bs[nb][ac + 3][ar]      = b0.w;
            Bs[nb][ac + 0][ar + 64] = b1.x; Bs[nb][ac + 1][ar + 64] = b1.y;
            Bs[nb][ac + 2][ar + 64] = b1.z; Bs[nb][ac + 3][ar + 64] = b1.w;
            __syncthreads();
            buf = nb;
        }
    }

    float bv[8];
#pragma unroll
    for (int j = 0; j < 4; j++) {
        bv[j]     = bias1[n0 + tn * 4 + j];
        bv[4 + j] = bias1[n0 + tn * 4 + 64 + j];
    }
    if (EPI == 0) {
#pragma unroll
        for (int j = 0; j < 4; j++) {
            bv[j]     += bias2[n0 + tn * 4 + j];
            bv[4 + j] += bias2[n0 + tn * 4 + 64 + j];
        }
    }
#pragma unroll
    for (int i2 = 0; i2 < 4; i2++) {
        float2 v[8];
#pragma unroll
        for (int j = 0; j < 8; j++) v[j] = unpack2(acc[i2][j]);
#pragma unroll
        for (int half = 0; half < 2; half++) {
            int m = m0 + tm * 8 + i2 * 2 + half;
            float r[8];
#pragma unroll
            for (int j = 0; j < 8; j++) {
                float x = (half ? v[j].y : v[j].x) + bv[j];
                if (EPI == 1) x = 1.0f / (1.0f + __expf(-x));
                r[j] = x;
            }
            *(float4*)&C[(size_t)m * N + n0 + tn * 4]      = make_float4(r[0], r[1], r[2], r[3]);
            *(float4*)&C[(size_t)m * N + n0 + tn * 4 + 64] = make_float4(r[4], r[5], r[6], r[7]);
        }
    }
}

// ---------------------------------------------------------------------------
// Recurrence v3: v2 lane-pair mapping + PADDED h halves + bigger reg split.
// thread (part=tid&1, colg=tid>>1) computes partial dots for cols
// {colg, colg+128} over j in [part*128, part*128+128); shfl_xor(1) combines.
// h storage: hb[buf][part*132 + i] holds h[part*128+i] — the 132-float pad
// puts the lane-pair's two broadcast chunks on DISJOINT banks (1 wf/load).
//   weights/thread: 128 ull = 108 in regs (54/col) + 10 in smem (5 u2/col)
// wf/warp/step: 32 h + 40 w = 72  (vs 112 in v1/v2) -> ~576 wf-cyc/step.
// ---------------------------------------------------------------------------
#define WRC 54   // ull weights in registers per col (j 0..107 of the half)
#define WSC 5    // ulonglong2 weights in smem per col (j 108..127 of the half)
#define HB_PAD 132
#define SCAN_SMEM (2 * WSC * 256 * (int)sizeof(ulonglong2) + 2 * 2 * HB_PAD * (int)sizeof(float))

__global__ void __launch_bounds__(256, 1)
rnn_scan(const float* __restrict__ W_hh, const float* __restrict__ prev,
         float* __restrict__ hn_out)
{
    extern __shared__ __align__(16) char smem_raw[];
    ulonglong2* wsu2 = (ulonglong2*)smem_raw;          // [2*WSC][256] -> 40 KB
    float* hb = (float*)(smem_raw + 2 * WSC * 256 * sizeof(ulonglong2)); // [2][2*HB_PAD]

    const int tid  = threadIdx.x;
    const int part = tid & 1;         // j-half: [part*128, part*128+128)
    const int colg = tid >> 1;        // 0..127
    const int b    = blockIdx.x;
    const int col_out = colg + part * 128;   // the column this lane outputs

    // Weights: rows colg and colg+128, j-half `part` (64 ull each)
    ull w0[WRC], w1[WRC];
    {
        const ull* wr0 = (const ull*)(W_hh + (size_t)colg * NH + part * 128);
        const ull* wr1 = (const ull*)(W_hh + (size_t)(colg + 128) * NH + part * 128);
#pragma unroll
        for (int q = 0; q < WRC; q++) { w0[q] = wr0[q]; w1[q] = wr1[q]; }
#pragma unroll
        for (int i = 0; i < WSC; i++) {
            wsu2[i * 256 + tid]         = make_ulonglong2(wr0[WRC + 2 * i], wr0[WRC + 2 * i + 1]);
            wsu2[(WSC + i) * 256 + tid] = make_ulonglong2(wr1[WRC + 2 * i], wr1[WRC + 2 * i + 1]);
        }
    }

    // h0: h[j] lives at hb[0][(j>>7)*HB_PAD + (j&127)]
    hb[(tid >> 7) * HB_PAD + (tid & 127)] = prev[b * NH + tid];
    __syncthreads();

    const float* xrow  = g_xproj  + ((size_t)b * NT) * NH + col_out;
    float*       hidro = g_hidden + ((size_t)b * NT) * NH + col_out;
    float xp0 = xrow[0];
    float xp1 = xrow[NH];

    int p = 0;
    for (int t = 0; t < NT; t++) {
        float xp = xp0;
        xp0 = xp1;
        if (t + 2 < NT) xp1 = xrow[(size_t)(t + 2) * NH];   // depth-2 prefetch

        // this thread reads h[part*128 .. +128) : 32 LDS.128, 1 wf each (pad)
        const ulonglong2* hp = (const ulonglong2*)(hb + p * 2 * HB_PAD + part * HB_PAD);
        ull c0a = 0ull, c0b = 0ull, c1a = 0ull, c1b = 0ull;
#pragma unroll
        for (int q = 0; q < 27; q++) {
            ulonglong2 hv = hp[q];
            c0a = fma2(w0[2 * q],     hv.x, c0a);
            c0b = fma2(w0[2 * q + 1], hv.y, c0b);
            c1a = fma2(w1[2 * q],     hv.x, c1a);
            c1b = fma2(w1[2 * q + 1], hv.y, c1b);
        }
#pragma unroll
        for (int q = 27; q < 32; q++) {
            ulonglong2 hv = hp[q];
            ulonglong2 u0 = wsu2[(q - 27) * 256 + tid];
            ulonglong2 u1 = wsu2[(WSC + q - 27) * 256 + tid];
            c0a = fma2(u0.x, hv.x, c0a);
            c0b = fma2(u0.y, hv.y, c0b);
            c1a = fma2(u1.x, hv.x, c1a);
            c1b = fma2(u1.y, hv.y, c1b);
        }
        float2 e0 = unpack2(c0a), e1 = unpack2(c0b);
        float2 e2 = unpack2(c1a), e3 = unpack2(c1b);
        float t0 = (e0.x + e0.y) + (e1.x + e1.y);   // partial for col colg
        float t1 = (e2.x + e2.y) + (e3.x + e3.y);   // partial for col colg+128
        float tot0 = t0 + __shfl_xor_sync(0xffffffffu, t0, 1);
        float tot1 = t1 + __shfl_xor_sync(0xffffffffu, t1, 1);

        float h = fmaxf((part ? tot1 : tot0) + xp, 0.0f);
        hb[(p ^ 1) * 2 * HB_PAD + part * HB_PAD + colg] = h;   // next step's h
        // streaming store: g_hidden is consumed only by a later kernel
        asm volatile("st.global.cs.f32 [%0], %1;"
                     :: "l"(hidro + (size_t)t * NH), "f"(fminf(h, 1.0f)) : "memory");
        if (t == NT - 1) hn_out[b * NH + col_out] = h;
        __syncthreads();
        p ^= 1;
    }
}

// ---------------------------------------------------------------------------
extern "C" void kernel_launch(void* const* d_in, const int* in_sizes, int n_in,
                              void* d_out, int out_size)
{
    const float* sentence = (const float*)d_in[0];
    const float* prev     = (const float*)d_in[1];
    const float* W_ih     = (const float*)d_in[2];
    const float* b_ih     = (const float*)d_in[3];
    const float* W_hh     = (const float*)d_in[4];
    const float* b_hh     = (const float*)d_in[5];
    const float* W_out    = (const float*)d_in[6];
    const float* b_out    = (const float*)d_in[7];
    float* out = (float*)d_out;

    float* xproj = nullptr;
    float* hidden = nullptr;
    cudaGetSymbolAddress((void**)&xproj, g_xproj);
    cudaGetSymbolAddress((void**)&hidden, g_hidden);

    // idempotent, non-enqueuing attribute set: capture-safe
    cudaFuncSetAttribute(rnn_scan, cudaFuncAttributeMaxDynamicSharedMemorySize,
                         SCAN_SMEM);

    // Phase 1: x_proj = sentence @ W_ih^T + (b_ih + b_hh)
    gemm_nt<0><<<dim3(NH / 128, MR / 128), 256>>>(sentence, W_ih, b_ih, b_hh,
                                                  xproj, MR, NH, NV);
    // Phase 2: sequential scan; writes g_hidden and h_n (tail of d_out)
    rnn_scan<<<NB, 256, SCAN_SMEM>>>(W_hh, prev, out + (size_t)MR * NO);
    // Phase 3: tags = sigmoid(hidden @ W_out^T + b_out)
    gemm_nt<1><<<dim3(NO / 128, MR / 128), 256>>>(hidden, W_out, b_out, nullptr,
                                                  out, MR, NO, NH);
}

// round 17
// speedup vs baseline: 1.0819x; 1.0819x over previous
#include <cuda_runtime.h>
#include <math.h>

#define NB 64
#define NT 512
#define NV 512
#define NH 256
#define NO 512
#define MR (NB * NT)   // 32768 rows

// Scratch (allocation-free rule: __device__ globals)
__device__ float g_xproj[(size_t)MR * NH];   // x@W_ih^T + b_ih + b_hh
__device__ float g_hidden[(size_t)MR * NH];  // min(relu(h),1)

typedef unsigned long long ull;

__device__ __forceinline__ ull fma2(ull a, ull b, ull c) {
    ull d;
    asm("fma.rn.f32x2 %0, %1, %2, %3;" : "=l"(d) : "l"(a), "l"(b), "l"(c));
    return d;
}
__device__ __forceinline__ ull pack2(float lo, float hi) {
    ull r;
    unsigned int l = __float_as_uint(lo), h = __float_as_uint(hi);
    asm("mov.b64 %0, {%1, %2};" : "=l"(r) : "r"(l), "r"(h));
    return r;
}
__device__ __forceinline__ float2 unpack2(ull v) {
    unsigned int l, h;
    asm("mov.b64 {%0, %1}, %2;" : "=r"(l), "=r"(h) : "l"(v));
    return make_float2(__uint_as_float(l), __uint_as_float(h));
}

// ---------------------------------------------------------------------------
// GEMM (R4 version — measured ~173us): BM=BN=128, BK=16, 256 threads,
// 8x8 micro-tile via f32x2 packed FMA, static double-buffered smem,
// one __syncthreads per k-tile.
// EPI==0: + bias1[n] + bias2[n]      EPI==1: sigmoid(x + bias1[n]) via __expf
// ---------------------------------------------------------------------------
template<int EPI>
__global__ void __launch_bounds__(256, 2)
gemm_nt(const float* __restrict__ A, const float* __restrict__ Bw,
        const float* __restrict__ bias1, const float* __restrict__ bias2,
        float* __restrict__ C, int M, int N, int K)
{
    __shared__ __align__(16) float As[2][16][132];
    __shared__ __align__(16) float Bs[2][16][132];
    const int tid = threadIdx.x;
    const int m0 = blockIdx.y << 7;
    const int n0 = blockIdx.x << 7;
    const int ar = tid >> 2;          // 0..63
    const int ac = (tid & 3) << 2;    // 0,4,8,12
    const float* Ag = A  + (size_t)(m0 + ar) * K + ac;
    const float* Bg = Bw + (size_t)(n0 + ar) * K + ac;
    const int tm = tid >> 4;          // 0..15 (row group of 8)
    const int tn = tid & 15;          // 0..15 (col group: tn*4 and tn*4+64)

    ull acc[4][8];
#pragma unroll
    for (int i = 0; i < 4; i++)
#pragma unroll
        for (int j = 0; j < 8; j++) acc[i][j] = 0ull;

    float4 a0 = *(const float4*)(Ag);
    float4 a1 = *(const float4*)(Ag + (size_t)64 * K);
    float4 b0 = *(const float4*)(Bg);
    float4 b1 = *(const float4*)(Bg + (size_t)64 * K);
    int buf = 0;
    {
        As[0][ac + 0][ar]      = a0.x; As[0][ac + 1][ar]      = a0.y;
        As[0][ac + 2][ar]      = a0.z; As[0][ac + 3][ar]      = a0.w;
        As[0][ac + 0][ar + 64] = a1.x; As[0][ac + 1][ar + 64] = a1.y;
        As[0][ac + 2][ar + 64] = a1.z; As[0][ac + 3][ar + 64] = a1.w;
        Bs[0][ac + 0][ar]      = b0.x; Bs[0][ac + 1][ar]      = b0.y;
        Bs[0][ac + 2][ar]      = b0.z; Bs[0][ac + 3][ar]      = b0.w;
        Bs[0][ac + 0][ar + 64] = b1.x; Bs[0][ac + 1][ar + 64] = b1.y;
        Bs[0][ac + 2][ar + 64] = b1.z; Bs[0][ac + 3][ar + 64] = b1.w;
    }
    __syncthreads();

    for (int k0 = 0; k0 < K; k0 += 16) {
        const bool more = (k0 + 16) < K;
        if (more) {
            Ag += 16; Bg += 16;
            a0 = *(const float4*)(Ag);
            a1 = *(const float4*)(Ag + (size_t)64 * K);
            b0 = *(const float4*)(Bg);
            b1 = *(const float4*)(Bg + (size_t)64 * K);
        }
#pragma unroll
        for (int k = 0; k < 16; k++) {
            ulonglong2 aA = *(const ulonglong2*)&As[buf][k][tm * 8];
            ulonglong2 aB = *(const ulonglong2*)&As[buf][k][tm * 8 + 4];
            float4 bA = *(const float4*)&Bs[buf][k][tn * 4];
            float4 bB = *(const float4*)&Bs[buf][k][tn * 4 + 64];
            ull a2[4] = { aA.x, aA.y, aB.x, aB.y };
            ull bb[8] = { pack2(bA.x, bA.x), pack2(bA.y, bA.y),
                          pack2(bA.z, bA.z), pack2(bA.w, bA.w),
                          pack2(bB.x, bB.x), pack2(bB.y, bB.y),
                          pack2(bB.z, bB.z), pack2(bB.w, bB.w) };
#pragma unroll
            for (int j = 0; j < 8; j++)
#pragma unroll
                for (int i = 0; i < 4; i++)
                    acc[i][j] = fma2(a2[i], bb[j], acc[i][j]);
        }
        if (more) {
            int nb = buf ^ 1;
            As[nb][ac + 0][ar]      = a0.x; As[nb][ac + 1][ar]      = a0.y;
            As[nb][ac + 2][ar]      = a0.z; As[nb][ac + 3][ar]      = a0.w;
            As[nb][ac + 0][ar + 64] = a1.x; As[nb][ac + 1][ar + 64] = a1.y;
            As[nb][ac + 2][ar + 64] = a1.z; As[nb][ac + 3][ar + 64] = a1.w;
            Bs[nb][ac + 0][ar]      = b0.x; Bs[nb][ac + 1][ar]      = b0.y;
            Bs[nb][ac + 2][ar]      = b0.z; Bs[nb][ac + 3][ar]      = b0.w;
            Bs[nb][ac + 0][ar + 64] = b1.x; Bs[nb][ac + 1][ar + 64] = b1.y;
            Bs[nb][ac + 2][ar + 64] = b1.z; Bs[nb][ac + 3][ar + 64] = b1.w;
            __syncthreads();
            buf = nb;
        }
    }

    float bv[8];
#pragma unroll
    for (int j = 0; j < 4; j++) {
        bv[j]     = bias1[n0 + tn * 4 + j];
        bv[4 + j] = bias1[n0 + tn * 4 + 64 + j];
    }
    if (EPI == 0) {
#pragma unroll
        for (int j = 0; j < 4; j++) {
            bv[j]     += bias2[n0 + tn * 4 + j];
            bv[4 + j] += bias2[n0 + tn * 4 + 64 + j];
        }
    }
#pragma unroll
    for (int i2 = 0; i2 < 4; i2++) {
        float2 v[8];
#pragma unroll
        for (int j = 0; j < 8; j++) v[j] = unpack2(acc[i2][j]);
#pragma unroll
        for (int half = 0; half < 2; half++) {
            int m = m0 + tm * 8 + i2 * 2 + half;
            float r[8];
#pragma unroll
            for (int j = 0; j < 8; j++) {
                float x = (half ? v[j].y : v[j].x) + bv[j];
                if (EPI == 1) x = 1.0f / (1.0f + __expf(-x));
                r[j] = x;
            }
            *(float4*)&C[(size_t)m * N + n0 + tn * 4]      = make_float4(r[0], r[1], r[2], r[3]);
            *(float4*)&C[(size_t)m * N + n0 + tn * 4 + 64] = make_float4(r[4], r[5], r[6], r[7]);
        }
    }
}

// ---------------------------------------------------------------------------
// Recurrence v4 = v2 config (WRC=52, WSC=6 — compiled clean, no spill) plus
// ONLY the h-pad: hb[buf][part*HB_PAD + i] with HB_PAD=132 puts the lane
// pair's two broadcast chunks 528B apart -> disjoint banks -> 1 wf per h
// LDS.128 (32 wf/warp instead of 64).
// thread (part=tid&1, colg=tid>>1): partial dots for cols {colg, colg+128}
// over j-half `part`; shfl_xor(1) combines partials.
// wf/warp/step: 32 h + 48 weight = 80 -> ~640 wf-cyc/SM (vs 896 in v1b).
// ---------------------------------------------------------------------------
#define WRC 52   // ull weights in registers per col (j 0..103 of the half)
#define WSC 6    // ulonglong2 weights in smem per col (j 104..127 of the half)
#define HB_PAD 132
#define SCAN_SMEM (2 * WSC * 256 * (int)sizeof(ulonglong2) + 2 * 2 * HB_PAD * (int)sizeof(float))

__global__ void __launch_bounds__(256, 1)
rnn_scan(const float* __restrict__ W_hh, const float* __restrict__ prev,
         float* __restrict__ hn_out)
{
    extern __shared__ __align__(16) char smem_raw[];
    ulonglong2* wsu2 = (ulonglong2*)smem_raw;          // [2*WSC][256] -> 48 KB
    float* hb = (float*)(smem_raw + 2 * WSC * 256 * sizeof(ulonglong2)); // [2][2*HB_PAD]

    const int tid  = threadIdx.x;
    const int part = tid & 1;         // j-half: [part*128, part*128+128)
    const int colg = tid >> 1;        // 0..127
    const int b    = blockIdx.x;
    const int col_out = colg + part * 128;   // the column this lane outputs

    // Weights: rows colg and colg+128, j-half `part` (64 ull each)
    ull w0[WRC], w1[WRC];
    {
        const ull* wr0 = (const ull*)(W_hh + (size_t)colg * NH + part * 128);
        const ull* wr1 = (const ull*)(W_hh + (size_t)(colg + 128) * NH + part * 128);
#pragma unroll
        for (int q = 0; q < WRC; q++) { w0[q] = wr0[q]; w1[q] = wr1[q]; }
#pragma unroll
        for (int i = 0; i < WSC; i++) {
            wsu2[i * 256 + tid]         = make_ulonglong2(wr0[WRC + 2 * i], wr0[WRC + 2 * i + 1]);
            wsu2[(WSC + i) * 256 + tid] = make_ulonglong2(wr1[WRC + 2 * i], wr1[WRC + 2 * i + 1]);
        }
    }

    // h0: h[j] lives at hb[0][(j>>7)*HB_PAD + (j&127)]
    hb[(tid >> 7) * HB_PAD + (tid & 127)] = prev[b * NH + tid];
    __syncthreads();

    const float* xrow  = g_xproj  + ((size_t)b * NT) * NH + col_out;
    float*       hidro = g_hidden + ((size_t)b * NT) * NH + col_out;
    float xp0 = xrow[0];
    float xp1 = xrow[NH];

    int p = 0;
    for (int t = 0; t < NT; t++) {
        float xp = xp0;
        xp0 = xp1;
        if (t + 2 < NT) xp1 = xrow[(size_t)(t + 2) * NH];   // depth-2 prefetch

        // this thread reads h[part*128 .. +128) : 32 LDS.128, 1 wf each (pad)
        const ulonglong2* hp = (const ulonglong2*)(hb + p * 2 * HB_PAD + part * HB_PAD);
        ull c0a = 0ull, c0b = 0ull, c1a = 0ull, c1b = 0ull;
#pragma unroll
        for (int q = 0; q < 26; q++) {
            ulonglong2 hv = hp[q];
            c0a = fma2(w0[2 * q],     hv.x, c0a);
            c0b = fma2(w0[2 * q + 1], hv.y, c0b);
            c1a = fma2(w1[2 * q],     hv.x, c1a);
            c1b = fma2(w1[2 * q + 1], hv.y, c1b);
        }
#pragma unroll
        for (int q = 26; q < 32; q++) {
            ulonglong2 hv = hp[q];
            ulonglong2 u0 = wsu2[(q - 26) * 256 + tid];
            ulonglong2 u1 = wsu2[(WSC + q - 26) * 256 + tid];
            c0a = fma2(u0.x, hv.x, c0a);
            c0b = fma2(u0.y, hv.y, c0b);
            c1a = fma2(u1.x, hv.x, c1a);
            c1b = fma2(u1.y, hv.y, c1b);
        }
        float2 e0 = unpack2(c0a), e1 = unpack2(c0b);
        float2 e2 = unpack2(c1a), e3 = unpack2(c1b);
        float t0 = (e0.x + e0.y) + (e1.x + e1.y);   // partial for col colg
        float t1 = (e2.x + e2.y) + (e3.x + e3.y);   // partial for col colg+128
        float tot0 = t0 + __shfl_xor_sync(0xffffffffu, t0, 1);
        float tot1 = t1 + __shfl_xor_sync(0xffffffffu, t1, 1);

        float h = fmaxf((part ? tot1 : tot0) + xp, 0.0f);
        hb[(p ^ 1) * 2 * HB_PAD + part * HB_PAD + colg] = h;   // next step's h
        // streaming store: g_hidden is consumed only by a later kernel
        asm volatile("st.global.cs.f32 [%0], %1;"
                     :: "l"(hidro + (size_t)t * NH), "f"(fminf(h, 1.0f)) : "memory");
        if (t == NT - 1) hn_out[b * NH + col_out] = h;
        __syncthreads();
        p ^= 1;
    }
}

// ---------------------------------------------------------------------------
extern "C" void kernel_launch(void* const* d_in, const int* in_sizes, int n_in,
                              void* d_out, int out_size)
{
    const float* sentence = (const float*)d_in[0];
    const float* prev     = (const float*)d_in[1];
    const float* W_ih     = (const float*)d_in[2];
    const float* b_ih     = (const float*)d_in[3];
    const float* W_hh     = (const float*)d_in[4];
    const float* b_hh     = (const float*)d_in[5];
    const float* W_out    = (const float*)d_in[6];
    const float* b_out    = (const float*)d_in[7];
    float* out = (float*)d_out;

    float* xproj = nullptr;
    float* hidden = nullptr;
    cudaGetSymbolAddress((void**)&xproj, g_xproj);
    cudaGetSymbolAddress((void**)&hidden, g_hidden);

    // idempotent, non-enqueuing attribute set: capture-safe
    cudaFuncSetAttribute(rnn_scan, cudaFuncAttributeMaxDynamicSharedMemorySize,
                         SCAN_SMEM);

    // Phase 1: x_proj = sentence @ W_ih^T + (b_ih + b_hh)
    gemm_nt<0><<<dim3(NH / 128, MR / 128), 256>>>(sentence, W_ih, b_ih, b_hh,
                                                  xproj, MR, NH, NV);
    // Phase 2: sequential scan; writes g_hidden and h_n (tail of d_out)
    rnn_scan<<<NB, 256, SCAN_SMEM>>>(W_hh, prev, out + (size_t)MR * NO);
    // Phase 3: tags = sigmoid(hidden @ W_out^T + b_out)
    gemm_nt<1><<<dim3(NO / 128, MR / 128), 256>>>(hidden, W_out, b_out, nullptr,
                                                  out, MR, NO, NH);
}